// round 1
// baseline (speedup 1.0000x reference)
#include <cuda_runtime.h>
#include <math.h>

#define DIM    256
#define NHALF  8192
#define NROWS  16384
#define BM     128
#define BK     16
#define NBLK   128                       /* 16384 / 128 */
#define NPAIRS ((NBLK * (NBLK + 1)) / 2) /* 8256 upper-triangle blocks */
#define KSTEPS (DIM / BK)                /* 16 */

static __device__ double g_acc[3];       /* ss, tt, st sums */
static __device__ float  g_norms[NROWS];

/* ---------------- packed f32x2 helpers (Blackwell FFMA2 via PTX) -------- */
__device__ __forceinline__ unsigned long long dup2(float x) {
    unsigned long long r;
    asm("mov.b64 %0, {%1, %1};" : "=l"(r) : "f"(x));
    return r;
}
__device__ __forceinline__ unsigned long long pack2(float lo, float hi) {
    unsigned long long r;
    asm("mov.b64 %0, {%1, %2};" : "=l"(r) : "f"(lo), "f"(hi));
    return r;
}
__device__ __forceinline__ void ffma2(unsigned long long &acc,
                                      unsigned long long a,
                                      unsigned long long b) {
    asm("fma.rn.f32x2 %0, %1, %2, %0;" : "+l"(acc) : "l"(a), "l"(b));
}
__device__ __forceinline__ void unpack2(unsigned long long v, float &lo, float &hi) {
    asm("mov.b64 {%0, %1}, %2;" : "=f"(lo), "=f"(hi) : "l"(v));
}

/* ---------------- init: zero accumulators ------------------------------- */
__global__ void mmd_init() {
    if (threadIdx.x < 3) g_acc[threadIdx.x] = 0.0;
}

/* ---------------- row squared norms (one warp per row) ------------------ */
__global__ void mmd_norms(const float* __restrict__ src,
                          const float* __restrict__ tgt) {
    int w    = (int)((blockIdx.x * blockDim.x + threadIdx.x) >> 5);
    int lane = threadIdx.x & 31;
    if (w >= NROWS) return;
    const float* p = (w < NHALF) ? src + (size_t)w * DIM
                                 : tgt + (size_t)(w - NHALF) * DIM;
    float s = 0.f;
#pragma unroll
    for (int j = 0; j < DIM / 32; j++) {
        float v = p[lane + 32 * j];
        s = fmaf(v, v, s);
    }
#pragma unroll
    for (int o = 16; o; o >>= 1) s += __shfl_xor_sync(0xffffffffu, s, o);
    if (lane == 0) g_norms[w] = s;
}

/* ---------------- main: tiled Gram + exp epilogue ------------------------ */
__global__ void __launch_bounds__(256, 2)
mmd_main(const float* __restrict__ src, const float* __restrict__ tgt) {
    __shared__ float As[2][BK][BM];
    __shared__ float Bs[2][BK][BM];
    __shared__ float red[8];

    /* decode linear block id -> (bi, bj) with bi <= bj */
    int t = (int)blockIdx.x;
    int bi = 0;
    while (t >= NBLK - bi) { t -= NBLK - bi; bi++; }
    int bj = bi + t;

    const float* baseA = (bi < 64) ? src + (size_t)bi * BM * DIM
                                   : tgt + (size_t)(bi - 64) * BM * DIM;
    const float* baseB = (bj < 64) ? src + (size_t)bj * BM * DIM
                                   : tgt + (size_t)(bj - 64) * BM * DIM;

    const int tid = (int)threadIdx.x;
    const int lr  = tid >> 2;          /* 0..63  : row within half-tile   */
    const int lc  = (tid & 3) << 2;    /* 0,4,8,12 : k offset             */

    const int tm = tid & 15;           /* 0..15 */
    const int tn = tid >> 4;           /* 0..15 */
    const int m0 = tm << 2;            /* frag rows: m0..m0+3, m0+64..m0+67 */
    const int n0 = tn << 2;            /* frag cols: n0..n0+3, n0+64..n0+67 */

    unsigned long long acc[8][4];
#pragma unroll
    for (int i = 0; i < 8; i++)
#pragma unroll
        for (int j = 0; j < 4; j++) acc[i][j] = 0ull;

    float4 ra[2], rb[2];

    /* prologue: load k-tile 0 */
#pragma unroll
    for (int rr = 0; rr < 2; rr++) {
        ra[rr] = *(const float4*)(baseA + (size_t)(lr + rr * 64) * DIM + lc);
        rb[rr] = *(const float4*)(baseB + (size_t)(lr + rr * 64) * DIM + lc);
    }
#pragma unroll
    for (int rr = 0; rr < 2; rr++) {
        int r = lr + rr * 64;
        As[0][lc + 0][r] = ra[rr].x; As[0][lc + 1][r] = ra[rr].y;
        As[0][lc + 2][r] = ra[rr].z; As[0][lc + 3][r] = ra[rr].w;
        Bs[0][lc + 0][r] = rb[rr].x; Bs[0][lc + 1][r] = rb[rr].y;
        Bs[0][lc + 2][r] = rb[rr].z; Bs[0][lc + 3][r] = rb[rr].w;
    }
    __syncthreads();

    int cur = 0;
    for (int kb = 0; kb < KSTEPS; kb++) {
        if (kb < KSTEPS - 1) {
            int k0 = (kb + 1) * BK;
#pragma unroll
            for (int rr = 0; rr < 2; rr++) {
                ra[rr] = *(const float4*)(baseA + (size_t)(lr + rr * 64) * DIM + k0 + lc);
                rb[rr] = *(const float4*)(baseB + (size_t)(lr + rr * 64) * DIM + k0 + lc);
            }
        }
#pragma unroll
        for (int kk = 0; kk < BK; kk++) {
            float4 av0 = *(const float4*)&As[cur][kk][m0];
            float4 av1 = *(const float4*)&As[cur][kk][m0 + 64];
            float4 bv0 = *(const float4*)&Bs[cur][kk][n0];
            float4 bv1 = *(const float4*)&Bs[cur][kk][n0 + 64];
            unsigned long long b2v[4];
            b2v[0] = pack2(bv0.x, bv0.y); b2v[1] = pack2(bv0.z, bv0.w);
            b2v[2] = pack2(bv1.x, bv1.y); b2v[3] = pack2(bv1.z, bv1.w);
            float av[8] = {av0.x, av0.y, av0.z, av0.w,
                           av1.x, av1.y, av1.z, av1.w};
#pragma unroll
            for (int i = 0; i < 8; i++) {
                unsigned long long ad = dup2(av[i]);
#pragma unroll
                for (int j = 0; j < 4; j++) ffma2(acc[i][j], ad, b2v[j]);
            }
        }
        if (kb < KSTEPS - 1) {
            int nxt = cur ^ 1;
#pragma unroll
            for (int rr = 0; rr < 2; rr++) {
                int r = lr + rr * 64;
                As[nxt][lc + 0][r] = ra[rr].x; As[nxt][lc + 1][r] = ra[rr].y;
                As[nxt][lc + 2][r] = ra[rr].z; As[nxt][lc + 3][r] = ra[rr].w;
                Bs[nxt][lc + 0][r] = rb[rr].x; Bs[nxt][lc + 1][r] = rb[rr].y;
                Bs[nxt][lc + 2][r] = rb[rr].z; Bs[nxt][lc + 3][r] = rb[rr].w;
            }
            __syncthreads();
            cur = nxt;
        }
    }

    /* ---------------- epilogue: d2 -> exp -> sum ---------------- */
    float nm[8], nn[8];
#pragma unroll
    for (int i = 0; i < 8; i++) {
        int m = (i < 4) ? (m0 + i) : (m0 + 64 + (i - 4));
        nm[i] = g_norms[bi * BM + m];
    }
#pragma unroll
    for (int j = 0; j < 8; j++) {
        int n = (j < 4) ? (n0 + j) : (n0 + 64 + (j - 4));
        nn[j] = g_norms[bj * BM + n];
    }

    float lsum = 0.f;
#pragma unroll
    for (int i = 0; i < 8; i++) {
#pragma unroll
        for (int j = 0; j < 4; j++) {
            float clo, chi;
            unpack2(acc[i][j], clo, chi);
            int jlo = (j < 2) ? (2 * j) : (4 + 2 * (j - 2));
            float d2a = fmaf(-2.f, clo, nm[i] + nn[jlo]);
            float d2b = fmaf(-2.f, chi, nm[i] + nn[jlo + 1]);
            d2a = fmaxf(d2a, 0.f);
            d2b = fmaxf(d2b, 0.f);
            /* exp underflows to 0 in fp32 beyond ~208; branch is
               warp-coherent false except on Gram diagonals */
            if (d2a < 200.f) lsum += expf(-0.5f * d2a);
            if (d2b < 200.f) lsum += expf(-0.5f * d2b);
        }
    }

    /* block reduce */
#pragma unroll
    for (int o = 16; o; o >>= 1) lsum += __shfl_xor_sync(0xffffffffu, lsum, o);
    if ((tid & 31) == 0) red[tid >> 5] = lsum;
    __syncthreads();
    if (tid == 0) {
        float bsum = 0.f;
#pragma unroll
        for (int w = 0; w < 8; w++) bsum += red[w];
        bool iS = (bi < 64), jS = (bj < 64);
        int region = iS ? (jS ? 0 : 2) : 1;      /* 0=ss, 1=tt, 2=st */
        double wgt = (region == 2) ? 1.0 : ((bi == bj) ? 1.0 : 2.0);
        atomicAdd(&g_acc[region], wgt * (double)bsum);
    }
}

/* ---------------- finalize ---------------------------------------------- */
__global__ void mmd_finalize(float* out) {
    if (threadIdx.x == 0) {
        double inv = 1.0 / ((double)NHALF * (double)NHALF);
        out[0] = (float)((g_acc[0] + g_acc[1] - 2.0 * g_acc[2]) * inv);
    }
}

/* ---------------- launch ------------------------------------------------- */
extern "C" void kernel_launch(void* const* d_in, const int* in_sizes, int n_in,
                              void* d_out, int out_size) {
    const float* src = (const float*)d_in[0];
    const float* tgt = (const float*)d_in[1];
    float* out = (float*)d_out;

    mmd_init<<<1, 32>>>();
    mmd_norms<<<(NROWS * 32) / 256, 256>>>(src, tgt);
    mmd_main<<<NPAIRS, 256>>>(src, tgt);
    mmd_finalize<<<1, 32>>>(out);
}

// round 3
// speedup vs baseline: 4.1250x; 4.1250x over previous
#include <cuda_runtime.h>
#include <cuda_bf16.h>
#include <math.h>
#include <stdint.h>

#define DIM    256
#define NHALF  8192
#define NROWS  16384
#define BM     128
#define NBLK   128
#define NPAIRS ((NBLK * (NBLK + 1)) / 2) /* 8256 */
#define FCAP   65536

/* dynamic smem layout: A[2][16384] | B[2][16384] | nmA[128] | nnB[128] */
#define SMEM_BYTES (65536 + 1024)

/* ------------------------- device globals ------------------------------- */
static __device__ double        g_acc[3];
static __device__ float         g_norms[NROWS];
static __device__ __nv_bfloat16 g_bf16[(size_t)NROWS * DIM];
static __device__ int           g_nflag;
static __device__ int2          g_flags[FCAP];

/* ------------------------- PTX helpers ---------------------------------- */
__device__ __forceinline__ uint32_t smem_u32(const void* p) {
    uint32_t a;
    asm("{ .reg .u64 t; cvta.to.shared.u64 t, %1; cvt.u32.u64 %0, t; }"
        : "=r"(a) : "l"(p));
    return a;
}
__device__ __forceinline__ void cp_async16(uint32_t dst, const void* src) {
    asm volatile("cp.async.cg.shared.global [%0], [%1], 16;"
                 :: "r"(dst), "l"(__cvta_generic_to_global(src)) : "memory");
}
#define CP_COMMIT() asm volatile("cp.async.commit_group;" ::: "memory")
#define CP_WAIT(N)  asm volatile("cp.async.wait_group %0;" :: "n"(N) : "memory")

__device__ __forceinline__ void ldmx4(uint32_t r[4], uint32_t addr) {
    asm volatile("ldmatrix.sync.aligned.m8n8.x4.shared.b16 {%0,%1,%2,%3}, [%4];"
                 : "=r"(r[0]), "=r"(r[1]), "=r"(r[2]), "=r"(r[3]) : "r"(addr));
}
__device__ __forceinline__ void mma16816(float c[4], const uint32_t a[4],
                                         uint32_t b0, uint32_t b1) {
    asm volatile(
        "mma.sync.aligned.m16n8k16.row.col.f32.bf16.bf16.f32 "
        "{%0,%1,%2,%3}, {%4,%5,%6,%7}, {%8,%9}, {%0,%1,%2,%3};"
        : "+f"(c[0]), "+f"(c[1]), "+f"(c[2]), "+f"(c[3])
        : "r"(a[0]), "r"(a[1]), "r"(a[2]), "r"(a[3]), "r"(b0), "r"(b1));
}
__device__ __forceinline__ uint32_t swz(uint32_t off) {
    return off ^ ((off >> 3) & 0x70u);
}

/* ------------------------- init ----------------------------------------- */
__global__ void mmd_init() {
    if (threadIdx.x < 3) g_acc[threadIdx.x] = 0.0;
    if (threadIdx.x == 0) g_nflag = 0;
}

/* -------------- prep: fp32->bf16 convert + fp32 row norms ---------------- */
__global__ void mmd_prep(const float* __restrict__ src,
                         const float* __restrict__ tgt) {
    int w    = (int)((blockIdx.x * blockDim.x + threadIdx.x) >> 5);
    int lane = threadIdx.x & 31;
    if (w >= NROWS) return;
    const float* p = (w < NHALF) ? src + (size_t)w * DIM
                                 : tgt + (size_t)(w - NHALF) * DIM;
    __nv_bfloat16* o = g_bf16 + (size_t)w * DIM;
    float s = 0.f;
#pragma unroll
    for (int c = 0; c < 2; c++) {
        int col = lane * 4 + c * 128;
        float4 v = *(const float4*)(p + col);
        s = fmaf(v.x, v.x, fmaf(v.y, v.y, fmaf(v.z, v.z, fmaf(v.w, v.w, s))));
        *(__nv_bfloat162*)(o + col)     = __floats2bfloat162_rn(v.x, v.y);
        *(__nv_bfloat162*)(o + col + 2) = __floats2bfloat162_rn(v.z, v.w);
    }
#pragma unroll
    for (int off = 16; off; off >>= 1) s += __shfl_xor_sync(0xffffffffu, s, off);
    if (lane == 0) g_norms[w] = s;
}

/* ------------------------- main mma.sync kernel -------------------------- */
__global__ void __launch_bounds__(256, 2) mmd_main_mma() {
    extern __shared__ char smem[];
    char* sA = smem;             /* [2][16384]: [128 rows][128B] swizzled */
    char* sB = smem + 32768;     /* [2][16384] */
    float* nmA = (float*)(smem + 65536);
    float* nnB = nmA + 128;

    const int tid  = (int)threadIdx.x;
    const int wid  = tid >> 5;
    const int lane = tid & 31;
    const int wm   = wid & 3;    /* warp row  (4): 32 M-rows each  */
    const int wn   = wid >> 2;   /* warp col  (2): 64 N-rows each  */

    /* decode linear block id -> (bi, bj), bi <= bj */
    int t = (int)blockIdx.x;
    int bi = 0;
    while (t >= NBLK - bi) { t -= NBLK - bi; bi++; }
    int bj = bi + t;

    const __nv_bfloat16* rowA = g_bf16 + (size_t)bi * BM * DIM;
    const __nv_bfloat16* rowB = g_bf16 + (size_t)bj * BM * DIM;

    if (tid < 128)       nmA[tid]       = g_norms[bi * BM + tid];
    else                 nnB[tid - 128] = g_norms[bj * BM + tid - 128];

    /* ---- cp.async chunk loader: chunk c covers k-cols [64c, 64c+64) ---- */
    const int lrow  = tid >> 1;      /* 0..127 */
    const int lhalf = tid & 1;       /* 0..1   */
    const uint32_t sAu = smem_u32(sA);
    const uint32_t sBu = smem_u32(sB);

#define LOAD_CHUNK(stage, c) do {                                          \
        const __nv_bfloat16* gA = rowA + (size_t)lrow * DIM + (c) * 64 + lhalf * 32; \
        const __nv_bfloat16* gB = rowB + (size_t)lrow * DIM + (c) * 64 + lhalf * 32; \
        uint32_t base = (uint32_t)(stage) * 16384u + (uint32_t)lrow * 128u \
                        + (uint32_t)lhalf * 64u;                           \
        _Pragma("unroll")                                                  \
        for (int i = 0; i < 4; i++) {                                      \
            uint32_t off = swz(base + i * 16u);                            \
            cp_async16(sAu + off, gA + i * 8);                             \
            cp_async16(sBu + off, gB + i * 8);                             \
        }                                                                  \
        CP_COMMIT();                                                       \
    } while (0)

    float acc[2][8][4];
#pragma unroll
    for (int i = 0; i < 2; i++)
#pragma unroll
        for (int j = 0; j < 8; j++)
#pragma unroll
            for (int k = 0; k < 4; k++) acc[i][j][k] = 0.f;

    const int row_in = lane & 15;
    const int grp    = lane >> 4;

#define DO_STAGE(stage) do {                                               \
        uint32_t aBase = sAu + (uint32_t)(stage) * 16384u;                 \
        uint32_t bBase = sBu + (uint32_t)(stage) * 16384u;                 \
        _Pragma("unroll")                                                  \
        for (int ks = 0; ks < 4; ks++) {                                   \
            uint32_t a[2][4];                                              \
            _Pragma("unroll")                                              \
            for (int i2 = 0; i2 < 2; i2++) {                               \
                uint32_t off = (uint32_t)(wm * 32 + i2 * 16 + row_in) * 128u \
                               + (uint32_t)(ks * 32 + grp * 16);           \
                ldmx4(a[i2], aBase + swz(off));                            \
            }                                                              \
            uint32_t b[4][4];                                              \
            _Pragma("unroll")                                              \
            for (int j2 = 0; j2 < 4; j2++) {                               \
                uint32_t off = (uint32_t)(wn * 64 + j2 * 16 + row_in) * 128u \
                               + (uint32_t)(ks * 32 + grp * 16);           \
                ldmx4(b[j2], bBase + swz(off));                            \
            }                                                              \
            _Pragma("unroll")                                              \
            for (int i2 = 0; i2 < 2; i2++)                                 \
                _Pragma("unroll")                                          \
                for (int j = 0; j < 8; j++)                                \
                    mma16816(acc[i2][j], a[i2],                            \
                             b[j >> 1][j & 1], b[j >> 1][2 + (j & 1)]);    \
        }                                                                  \
    } while (0)

    /* ---- pipelined mainloop over 4 K-chunks ---- */
    LOAD_CHUNK(0, 0);
    LOAD_CHUNK(1, 1);

    CP_WAIT(1); __syncthreads();
    DO_STAGE(0);
    __syncthreads();
    LOAD_CHUNK(0, 2);

    CP_WAIT(1); __syncthreads();
    DO_STAGE(1);
    __syncthreads();
    LOAD_CHUNK(1, 3);

    CP_WAIT(1); __syncthreads();
    DO_STAGE(0);

    CP_WAIT(0); __syncthreads();
    DO_STAGE(1);

    /* ---- epilogue: flag pairs with approx d2 < 64 ---- */
    const int r0 = lane >> 2;
    const int c0 = (lane & 3) * 2;
#pragma unroll
    for (int i2 = 0; i2 < 2; i2++) {
#pragma unroll
        for (int j = 0; j < 8; j++) {
#pragma unroll
            for (int h = 0; h < 2; h++) {
#pragma unroll
                for (int e = 0; e < 2; e++) {
                    int m = wm * 32 + i2 * 16 + r0 + h * 8;
                    int n = wn * 64 + j * 8 + c0 + e;
                    float d2 = nmA[m] + nnB[n] - 2.f * acc[i2][j][h * 2 + e];
                    if (d2 < 64.f) {
                        int idx = atomicAdd(&g_nflag, 1);
                        if (idx < FCAP)
                            g_flags[idx] = make_int2(bi * BM + m, bj * BM + n);
                    }
                }
            }
        }
    }
}

/* -------------- fixup: exact fp32 exp for flagged pairs ------------------ */
__global__ void mmd_fixup(const float* __restrict__ src,
                          const float* __restrict__ tgt) {
    int nf = g_nflag;
    if (nf > FCAP) nf = FCAP;
    int wg   = (int)((blockIdx.x * blockDim.x + threadIdx.x) >> 5);
    int lane = (int)(threadIdx.x & 31);
    int nw   = (int)((gridDim.x * blockDim.x) >> 5);
    for (int f = wg; f < nf; f += nw) {
        int2 pr = g_flags[f];
        const float* pa = (pr.x < NHALF) ? src + (size_t)pr.x * DIM
                                         : tgt + (size_t)(pr.x - NHALF) * DIM;
        const float* pb = (pr.y < NHALF) ? src + (size_t)pr.y * DIM
                                         : tgt + (size_t)(pr.y - NHALF) * DIM;
        float s = 0.f;
#pragma unroll
        for (int c = 0; c < 8; c++) {
            float d = pa[lane + 32 * c] - pb[lane + 32 * c];
            s = fmaf(d, d, s);
        }
#pragma unroll
        for (int off = 16; off; off >>= 1)
            s += __shfl_xor_sync(0xffffffffu, s, off);
        if (lane == 0) {
            float e = expf(-0.5f * fmaxf(s, 0.f));
            int region = (pr.x < NHALF) ? ((pr.y < NHALF) ? 0 : 2) : 1;
            double wgt = (region == 2) ? 1.0
                       : (((pr.x >> 7) == (pr.y >> 7)) ? 1.0 : 2.0);
            atomicAdd(&g_acc[region], wgt * (double)e);
        }
    }
}

/* ------------------------- finalize ------------------------------------- */
__global__ void mmd_finalize(float* out) {
    if (threadIdx.x == 0) {
        double inv = 1.0 / ((double)NHALF * (double)NHALF);
        out[0] = (float)((g_acc[0] + g_acc[1] - 2.0 * g_acc[2]) * inv);
    }
}

/* ------------------------- launch ---------------------------------------- */
extern "C" void kernel_launch(void* const* d_in, const int* in_sizes, int n_in,
                              void* d_out, int out_size) {
    const float* src = (const float*)d_in[0];
    const float* tgt = (const float*)d_in[1];
    float* out = (float*)d_out;

    static int configured = 0;
    if (!configured) {
        cudaFuncSetAttribute(mmd_main_mma,
                             cudaFuncAttributeMaxDynamicSharedMemorySize,
                             SMEM_BYTES);
        configured = 1;
    }

    mmd_init<<<1, 32>>>();
    mmd_prep<<<(NROWS * 32) / 256, 256>>>(src, tgt);
    mmd_main_mma<<<NPAIRS, 256, SMEM_BYTES>>>();
    mmd_fixup<<<64, 256>>>(src, tgt);
    mmd_finalize<<<1, 32>>>(out);
}